// round 1
// baseline (speedup 1.0000x reference)
#include <cuda_runtime.h>

// SigMMDLoss: B=4096 rows, T=4096, two input tensors (real, gen), scalar f32 output.
//
// Per-row (N = T-1 = 4095 increments dx_k = p[k+1]-p[k]):
//   f1 = sum dx
//   f3 = dt * sum (k+1)*dx  = p[N] - (sum_{j<N} p[j]) / N      (Abel summation)
//   f4 = sum cum(dx)*dx     = 0.5 * ((sum dx)^2 + sum dx^2)    (closed form)
//   f6 = sum dx^2
//   f8 = sum dx^3
// Time-only features are identical for real/gen and cancel exactly -> skipped.
// loss = sum_i ( (mean_real f_i - mean_gen f_i) )^2

#define T_LEN   4096
#define NROWS   4096
#define NBLOCKS (2 * NROWS)
#define THREADS 256
#define NFEAT   5

// Per-row feature scratch (non-atomic, fully overwritten each launch -> deterministic)
__device__ double g_feat[NBLOCKS][NFEAT];

__global__ __launch_bounds__(THREADS) void sigmmd_row_kernel(
    const float* __restrict__ real_paths,
    const float* __restrict__ gen_paths)
{
    const int bid = blockIdx.x;
    const float* base = (bid < NROWS) ? real_paths : gen_paths;
    const int row = bid & (NROWS - 1);
    const float* p = base + (size_t)row * T_LEN;
    const int tid = threadIdx.x;

    __shared__ float s_last[THREADS];
    __shared__ float s_w[THREADS / 32][4];

    // Each thread loads 16 contiguous floats as 4x float4 (front-batched for MLP)
    const float4* p4 = (const float4*)p;
    float4 a = p4[tid * 4 + 0];
    float4 b = p4[tid * 4 + 1];
    float4 c4 = p4[tid * 4 + 2];
    float4 d = p4[tid * 4 + 3];
    float v[16] = {a.x, a.y, a.z, a.w, b.x, b.y, b.z, b.w,
                   c4.x, c4.y, c4.z, c4.w, d.x, d.y, d.z, d.w};

    s_last[tid] = v[15];
    __syncthreads();
    // Chunk-boundary predecessor. Thread 0 uses its own v[0] -> phantom dx = 0,
    // which contributes exactly 0 to every accumulated quantity.
    float prev = (tid == 0) ? v[0] : s_last[tid - 1];

    float s1 = 0.f, q = 0.f, c = 0.f, sp = 0.f;
#pragma unroll
    for (int i = 0; i < 16; i++) {
        float dx = v[i] - prev;
        prev = v[i];
        s1 += dx;
        q = fmaf(dx, dx, q);
        float t = dx * dx;
        c = fmaf(t, dx, c);
        sp += v[i];
    }
    // sp must cover p[0..N-1] only: global last element (thread 255, v[15]) excluded
    if (tid == THREADS - 1) sp -= v[15];

    // Warp tree reduce (fp32, deterministic)
#pragma unroll
    for (int off = 16; off; off >>= 1) {
        s1 += __shfl_down_sync(0xffffffffu, s1, off);
        q  += __shfl_down_sync(0xffffffffu, q,  off);
        c  += __shfl_down_sync(0xffffffffu, c,  off);
        sp += __shfl_down_sync(0xffffffffu, sp, off);
    }
    const int wid = tid >> 5;
    if ((tid & 31) == 0) {
        s_w[wid][0] = s1; s_w[wid][1] = q; s_w[wid][2] = c; s_w[wid][3] = sp;
    }
    __syncthreads();

    if (tid == 0) {
        double S1 = 0, Q = 0, C = 0, SP = 0;
#pragma unroll
        for (int w = 0; w < THREADS / 32; w++) {
            S1 += (double)s_w[w][0];
            Q  += (double)s_w[w][1];
            C  += (double)s_w[w][2];
            SP += (double)s_w[w][3];
        }
        double pN = (double)s_last[THREADS - 1];
        double* o = g_feat[bid];
        o[0] = S1;                       // f1
        o[1] = pN - SP / 4095.0;         // f3
        o[2] = 0.5 * (S1 * S1 + Q);      // f4
        o[3] = Q;                        // f6
        o[4] = C;                        // f8
    }
}

__global__ __launch_bounds__(THREADS) void sigmmd_reduce_kernel(float* __restrict__ out)
{
    const int tid = threadIdx.x;
    double acc[NFEAT] = {0, 0, 0, 0, 0};
    // Fixed strided order -> deterministic
    for (int r = tid; r < NBLOCKS; r += THREADS) {
        double s = (r < NROWS) ? 1.0 : -1.0;
#pragma unroll
        for (int i = 0; i < NFEAT; i++) acc[i] += s * g_feat[r][i];
    }
    __shared__ double sm[THREADS][NFEAT];
#pragma unroll
    for (int i = 0; i < NFEAT; i++) sm[tid][i] = acc[i];
    __syncthreads();
    for (int stride = THREADS / 2; stride; stride >>= 1) {
        if (tid < stride) {
#pragma unroll
            for (int i = 0; i < NFEAT; i++) sm[tid][i] += sm[tid + stride][i];
        }
        __syncthreads();
    }
    if (tid == 0) {
        double loss = 0.0;
#pragma unroll
        for (int i = 0; i < NFEAT; i++) {
            double m = sm[0][i] / (double)NROWS;
            loss += m * m;
        }
        out[0] = (float)loss;
    }
}

extern "C" void kernel_launch(void* const* d_in, const int* in_sizes, int n_in,
                              void* d_out, int out_size)
{
    const float* real_paths = (const float*)d_in[0];
    const float* gen_paths  = (const float*)d_in[1];
    float* out = (float*)d_out;

    sigmmd_row_kernel<<<NBLOCKS, THREADS>>>(real_paths, gen_paths);
    sigmmd_reduce_kernel<<<1, THREADS>>>(out);
}

// round 2
// speedup vs baseline: 1.3235x; 1.3235x over previous
#include <cuda_runtime.h>

// SigMMDLoss: B=4096 rows, T=4096, two input tensors (real, gen), scalar f32 out.
//
// Per-row (N = T-1 = 4095 increments dx_k = p[k+1]-p[k]):
//   f1 = sum dx            = p[N] - p[0]                        (telescoped)
//   f3 = dt*sum (k+1)dx    = p[N] - (sum_{j<N} p[j]) / N        (Abel summation)
//   f4 = sum cum(dx)*dx    = 0.5 * (f1^2 + sum dx^2)            (closed form)
//   f6 = sum dx^2
//   f8 = sum dx^3
// Time-only features cancel exactly between real/gen -> skipped.
// loss = sum_i (mean_real f_i - mean_gen f_i)^2

#define T_LEN   4096
#define NROWS   4096
#define NBLOCKS (2 * NROWS)
#define THREADS 256
#define NFEAT   5

// Transposed per-row feature scratch: coalesced reads in the reduce kernel.
__device__ double g_feat[NFEAT][NBLOCKS];

// ---- packed f32x2 helpers (Blackwell; only reachable via PTX) ----
__device__ __forceinline__ unsigned long long pk2(float lo, float hi) {
    unsigned long long r;
    asm("mov.b64 %0, {%1, %2};" : "=l"(r) : "f"(lo), "f"(hi));
    return r;
}
__device__ __forceinline__ void upk2(unsigned long long p, float& lo, float& hi) {
    asm("mov.b64 {%0, %1}, %2;" : "=f"(lo), "=f"(hi) : "l"(p));
}
__device__ __forceinline__ unsigned long long fma2(unsigned long long a,
                                                   unsigned long long b,
                                                   unsigned long long c) {
    unsigned long long d;
    asm("fma.rn.f32x2 %0, %1, %2, %3;" : "=l"(d) : "l"(a), "l"(b), "l"(c));
    return d;
}
__device__ __forceinline__ unsigned long long add2(unsigned long long a,
                                                   unsigned long long b) {
    unsigned long long d;
    asm("add.rn.f32x2 %0, %1, %2;" : "=l"(d) : "l"(a), "l"(b));
    return d;
}
__device__ __forceinline__ unsigned long long mul2(unsigned long long a,
                                                   unsigned long long b) {
    unsigned long long d;
    asm("mul.rn.f32x2 %0, %1, %2;" : "=l"(d) : "l"(a), "l"(b));
    return d;
}

__global__ __launch_bounds__(THREADS) void sigmmd_row_kernel(
    const float* __restrict__ real_paths,
    const float* __restrict__ gen_paths)
{
    const int bid = blockIdx.x;
    const float* base = (bid < NROWS) ? real_paths : gen_paths;
    const int row = bid & (NROWS - 1);
    const float* p = base + (size_t)row * T_LEN;
    const int tid = threadIdx.x;

    __shared__ float s_last[THREADS];
    __shared__ float s_first;
    __shared__ float s_w[THREADS / 32][3];

    // 16 contiguous floats per thread, front-batched as 4x LDG.128
    const float4* p4 = (const float4*)p;
    float4 a = p4[tid * 4 + 0];
    float4 b = p4[tid * 4 + 1];
    float4 c4 = p4[tid * 4 + 2];
    float4 d = p4[tid * 4 + 3];
    float v[16] = {a.x, a.y, a.z, a.w, b.x, b.y, b.z, b.w,
                   c4.x, c4.y, c4.z, c4.w, d.x, d.y, d.z, d.w};

    s_last[tid] = v[15];
    if (tid == 0) s_first = v[0];
    __syncthreads();
    // Chunk-boundary predecessor. Thread 0 uses v[0] -> phantom dx = 0,
    // which contributes exactly 0 to every accumulated quantity.
    float prev = (tid == 0) ? v[0] : s_last[tid - 1];

    const unsigned long long NEG1 = pk2(-1.0f, -1.0f);
    unsigned long long qp = 0ull, cp = 0ull, spp = 0ull;   // (0.f, 0.f) pairs
#pragma unroll
    for (int j = 0; j < 8; j++) {
        unsigned long long cur = pk2(v[2 * j], v[2 * j + 1]);
        unsigned long long prv = pk2(prev, v[2 * j]);
        unsigned long long dx  = fma2(prv, NEG1, cur);     // cur - prv
        unsigned long long t   = mul2(dx, dx);             // dx^2
        qp  = add2(qp, t);                                  // sum dx^2
        cp  = fma2(t, dx, cp);                              // sum dx^3
        spp = add2(spp, cur);                               // sum p
        prev = v[2 * j + 1];
    }
    float ql, qh, cl, ch, sl, sh;
    upk2(qp, ql, qh); upk2(cp, cl, ch); upk2(spp, sl, sh);
    float q = ql + qh, c = cl + ch, sp = sl + sh;
    // sp must cover p[0..N-1] only: exclude the global last element
    if (tid == THREADS - 1) sp -= v[15];

    // Warp tree reduce (fp32, deterministic)
#pragma unroll
    for (int off = 16; off; off >>= 1) {
        q  += __shfl_down_sync(0xffffffffu, q,  off);
        c  += __shfl_down_sync(0xffffffffu, c,  off);
        sp += __shfl_down_sync(0xffffffffu, sp, off);
    }
    const int wid = tid >> 5;
    if ((tid & 31) == 0) {
        s_w[wid][0] = q; s_w[wid][1] = c; s_w[wid][2] = sp;
    }
    __syncthreads();

    if (tid == 0) {
        double Q = 0, C = 0, SP = 0;
#pragma unroll
        for (int w = 0; w < THREADS / 32; w++) {
            Q  += (double)s_w[w][0];
            C  += (double)s_w[w][1];
            SP += (double)s_w[w][2];
        }
        double p0 = (double)s_first;
        double pN = (double)s_last[THREADS - 1];
        double S1 = pN - p0;
        g_feat[0][bid] = S1;                   // f1
        g_feat[1][bid] = pN - SP / 4095.0;     // f3
        g_feat[2][bid] = 0.5 * (S1 * S1 + Q);  // f4
        g_feat[3][bid] = Q;                    // f6
        g_feat[4][bid] = C;                    // f8
    }
}

__global__ __launch_bounds__(THREADS) void sigmmd_reduce_kernel(float* __restrict__ out)
{
    const int tid = threadIdx.x;
    double acc[NFEAT] = {0, 0, 0, 0, 0};
    // Coalesced: consecutive threads read consecutive rows of one feature.
    // Sign split avoids a per-iteration multiply. Fixed order -> deterministic.
    for (int r = tid; r < NROWS; r += THREADS) {
#pragma unroll
        for (int i = 0; i < NFEAT; i++) acc[i] += g_feat[i][r];
    }
    for (int r = NROWS + tid; r < NBLOCKS; r += THREADS) {
#pragma unroll
        for (int i = 0; i < NFEAT; i++) acc[i] -= g_feat[i][r];
    }
    __shared__ double sm[THREADS][NFEAT];
#pragma unroll
    for (int i = 0; i < NFEAT; i++) sm[tid][i] = acc[i];
    __syncthreads();
    for (int stride = THREADS / 2; stride; stride >>= 1) {
        if (tid < stride) {
#pragma unroll
            for (int i = 0; i < NFEAT; i++) sm[tid][i] += sm[tid + stride][i];
        }
        __syncthreads();
    }
    if (tid == 0) {
        double loss = 0.0;
#pragma unroll
        for (int i = 0; i < NFEAT; i++) {
            double m = sm[0][i] / (double)NROWS;
            loss += m * m;
        }
        out[0] = (float)loss;
    }
}

extern "C" void kernel_launch(void* const* d_in, const int* in_sizes, int n_in,
                              void* d_out, int out_size)
{
    const float* real_paths = (const float*)d_in[0];
    const float* gen_paths  = (const float*)d_in[1];
    float* out = (float*)d_out;

    sigmmd_row_kernel<<<NBLOCKS, THREADS>>>(real_paths, gen_paths);
    sigmmd_reduce_kernel<<<1, THREADS>>>(out);
}

// round 3
// speedup vs baseline: 1.7765x; 1.3423x over previous
#include <cuda_runtime.h>

// SigMMDLoss: B=4096 rows, T=4096, two input tensors (real, gen), scalar f32 out.
//
// Per-row (N = T-1 = 4095 increments dx_k = p[k+1]-p[k]):
//   f1 = sum dx            = p[N] - p[0]                        (telescoped)
//   f3 = dt*sum (k+1)dx    = p[N] - (sum_{j<N} p[j]) / N        (Abel summation)
//   f4 = sum cum(dx)*dx    = 0.5 * (f1^2 + sum dx^2)            (closed form)
//   f6 = sum dx^2
//   f8 = sum dx^3
// Time-only features cancel exactly between real/gen -> skipped.
// loss = sum_i (mean_real f_i - mean_gen f_i)^2

#define T_LEN    4096
#define NROWS    4096
#define NBLOCKS  (2 * NROWS)
#define RT       128              // threads per row block
#define EPT      32               // elements per thread
#define NFEAT    5
#define P1_BLK   64               // partial-reduce blocks
#define ROWS_PB  (NBLOCKS / P1_BLK)   // 128 rows per partial block

// Transposed per-row feature scratch + per-block partials.
__device__ double g_feat[NFEAT][NBLOCKS];
__device__ double g_part[P1_BLK][NFEAT];

// ---- packed f32x2 helpers (Blackwell; only reachable via PTX) ----
__device__ __forceinline__ unsigned long long pk2(float lo, float hi) {
    unsigned long long r;
    asm("mov.b64 %0, {%1, %2};" : "=l"(r) : "f"(lo), "f"(hi));
    return r;
}
__device__ __forceinline__ void upk2(unsigned long long p, float& lo, float& hi) {
    asm("mov.b64 {%0, %1}, %2;" : "=f"(lo), "=f"(hi) : "l"(p));
}
__device__ __forceinline__ unsigned long long fma2(unsigned long long a,
                                                   unsigned long long b,
                                                   unsigned long long c) {
    unsigned long long d;
    asm("fma.rn.f32x2 %0, %1, %2, %3;" : "=l"(d) : "l"(a), "l"(b), "l"(c));
    return d;
}
__device__ __forceinline__ unsigned long long add2(unsigned long long a,
                                                   unsigned long long b) {
    unsigned long long d;
    asm("add.rn.f32x2 %0, %1, %2;" : "=l"(d) : "l"(a), "l"(b));
    return d;
}
__device__ __forceinline__ unsigned long long mul2(unsigned long long a,
                                                   unsigned long long b) {
    unsigned long long d;
    asm("mul.rn.f32x2 %0, %1, %2;" : "=l"(d) : "l"(a), "l"(b));
    return d;
}

__global__ __launch_bounds__(RT) void sigmmd_row_kernel(
    const float* __restrict__ real_paths,
    const float* __restrict__ gen_paths)
{
    const int bid = blockIdx.x;
    const float* base = (bid < NROWS) ? real_paths : gen_paths;
    const int row = bid & (NROWS - 1);
    const float* p = base + (size_t)row * T_LEN;
    const int tid = threadIdx.x;

    __shared__ float s_last[RT];
    __shared__ float s_first;
    __shared__ float s_w[RT / 32][3];

    // 32 contiguous floats per thread: 8 front-batched LDG.128 (streaming).
    const float4* p4 = (const float4*)p + tid * (EPT / 4);
    float4 ld[EPT / 4];
#pragma unroll
    for (int i = 0; i < EPT / 4; i++) ld[i] = __ldcs(p4 + i);
    float v[EPT];
#pragma unroll
    for (int i = 0; i < EPT / 4; i++) {
        v[4 * i + 0] = ld[i].x; v[4 * i + 1] = ld[i].y;
        v[4 * i + 2] = ld[i].z; v[4 * i + 3] = ld[i].w;
    }

    s_last[tid] = v[EPT - 1];
    if (tid == 0) s_first = v[0];
    __syncthreads();
    // Chunk-boundary predecessor. Thread 0 uses v[0] -> phantom dx = 0,
    // which contributes exactly 0 to every accumulated quantity.
    float prev = (tid == 0) ? v[0] : s_last[tid - 1];

    const unsigned long long NEG1 = pk2(-1.0f, -1.0f);
    unsigned long long qp = 0ull, cp = 0ull, spp = 0ull;   // (0.f, 0.f) pairs
#pragma unroll
    for (int j = 0; j < EPT / 2; j++) {
        unsigned long long cur = pk2(v[2 * j], v[2 * j + 1]);
        unsigned long long prv = pk2(prev, v[2 * j]);
        unsigned long long dx  = fma2(prv, NEG1, cur);     // cur - prv
        unsigned long long t   = mul2(dx, dx);             // dx^2
        qp  = add2(qp, t);                                  // sum dx^2
        cp  = fma2(t, dx, cp);                              // sum dx^3
        spp = add2(spp, cur);                               // sum p
        prev = v[2 * j + 1];
    }
    float ql, qh, cl, ch, sl, sh;
    upk2(qp, ql, qh); upk2(cp, cl, ch); upk2(spp, sl, sh);
    float q = ql + qh, c = cl + ch, sp = sl + sh;
    // sp must cover p[0..N-1] only: exclude the global last element
    if (tid == RT - 1) sp -= v[EPT - 1];

    // Warp tree reduce (fp32, deterministic)
#pragma unroll
    for (int off = 16; off; off >>= 1) {
        q  += __shfl_down_sync(0xffffffffu, q,  off);
        c  += __shfl_down_sync(0xffffffffu, c,  off);
        sp += __shfl_down_sync(0xffffffffu, sp, off);
    }
    const int wid = tid >> 5;
    if ((tid & 31) == 0) {
        s_w[wid][0] = q; s_w[wid][1] = c; s_w[wid][2] = sp;
    }
    __syncthreads();

    if (tid == 0) {
        double Q = 0, C = 0, SP = 0;
#pragma unroll
        for (int w = 0; w < RT / 32; w++) {
            Q  += (double)s_w[w][0];
            C  += (double)s_w[w][1];
            SP += (double)s_w[w][2];
        }
        double p0 = (double)s_first;
        double pN = (double)s_last[RT - 1];
        double S1 = pN - p0;
        g_feat[0][bid] = S1;                   // f1
        g_feat[1][bid] = pN - SP / 4095.0;     // f3
        g_feat[2][bid] = 0.5 * (S1 * S1 + Q);  // f4
        g_feat[3][bid] = Q;                    // f6
        g_feat[4][bid] = C;                    // f8
    }
}

// Stage 1: 64 blocks x 128 threads, one row per thread, coalesced per feature.
// Each block covers 128 contiguous rows (all same sign: 4096/128 = 32 blocks
// per tensor). Smem tree reduce -> one partial per block. Deterministic.
__global__ __launch_bounds__(ROWS_PB) void sigmmd_part_kernel()
{
    const int tid = threadIdx.x;
    const int r0 = blockIdx.x * ROWS_PB;
    const double sgn = (r0 < NROWS) ? 1.0 : -1.0;

    __shared__ double sm[ROWS_PB][NFEAT];
#pragma unroll
    for (int i = 0; i < NFEAT; i++) sm[tid][i] = g_feat[i][r0 + tid];
    __syncthreads();
    for (int stride = ROWS_PB / 2; stride; stride >>= 1) {
        if (tid < stride) {
#pragma unroll
            for (int i = 0; i < NFEAT; i++) sm[tid][i] += sm[tid + stride][i];
        }
        __syncthreads();
    }
    if (tid == 0) {
#pragma unroll
        for (int i = 0; i < NFEAT; i++) g_part[blockIdx.x][i] = sgn * sm[0][i];
    }
}

// Stage 2: one tiny block over 64 partials x 5 features (2.5 KB, L2-hot).
__global__ __launch_bounds__(P1_BLK) void sigmmd_final_kernel(float* __restrict__ out)
{
    const int tid = threadIdx.x;
    __shared__ double sm[P1_BLK][NFEAT];
#pragma unroll
    for (int i = 0; i < NFEAT; i++) sm[tid][i] = g_part[tid][i];
    __syncthreads();
    for (int stride = P1_BLK / 2; stride; stride >>= 1) {
        if (tid < stride) {
#pragma unroll
            for (int i = 0; i < NFEAT; i++) sm[tid][i] += sm[tid + stride][i];
        }
        __syncthreads();
    }
    if (tid == 0) {
        double loss = 0.0;
#pragma unroll
        for (int i = 0; i < NFEAT; i++) {
            double m = sm[0][i] / (double)NROWS;
            loss += m * m;
        }
        out[0] = (float)loss;
    }
}

extern "C" void kernel_launch(void* const* d_in, const int* in_sizes, int n_in,
                              void* d_out, int out_size)
{
    const float* real_paths = (const float*)d_in[0];
    const float* gen_paths  = (const float*)d_in[1];
    float* out = (float*)d_out;

    sigmmd_row_kernel<<<NBLOCKS, RT>>>(real_paths, gen_paths);
    sigmmd_part_kernel<<<P1_BLK, ROWS_PB>>>();
    sigmmd_final_kernel<<<1, P1_BLK>>>(out);
}

// round 4
// speedup vs baseline: 2.3804x; 1.3399x over previous
#include <cuda_runtime.h>

// SigMMDLoss: B=4096 rows, T=4096, two input tensors (real, gen), scalar f32 out.
//
// Per-row (N = T-1 = 4095 increments dx_k = p[k+1]-p[k]):
//   f1 = sum dx            = p[N] - p[0]                        (telescoped)
//   f3 = dt*sum (k+1)dx    = p[N] - (sum_{j<N} p[j]) / N        (Abel summation)
//   f4 = sum cum(dx)*dx    = 0.5 * (f1^2 + sum dx^2)            (closed form)
//   f6 = sum dx^2
//   f8 = sum dx^3
// Time-only features cancel exactly between real/gen -> skipped.
// loss = sum_i (mean_real f_i - mean_gen f_i)^2

#define T_LEN    4096
#define NROWS    4096
#define NBLOCKS  (2 * NROWS)
#define RT       128                  // threads per row block (4 warps)
#define WELEMS   1024                 // contiguous floats owned per warp
#define NFEAT    5
#define P1_BLK   64                   // partial-reduce blocks
#define ROWS_PB  (NBLOCKS / P1_BLK)   // 128 rows per partial block

__device__ double g_feat[NFEAT][NBLOCKS];
__device__ double g_part[P1_BLK][NFEAT];
__device__ int    g_ctr = 0;          // reset to 0 by last block each launch

// ---- packed f32x2 helpers (Blackwell; only reachable via PTX) ----
__device__ __forceinline__ unsigned long long pk2(float lo, float hi) {
    unsigned long long r;
    asm("mov.b64 %0, {%1, %2};" : "=l"(r) : "f"(lo), "f"(hi));
    return r;
}
__device__ __forceinline__ void upk2(unsigned long long p, float& lo, float& hi) {
    asm("mov.b64 {%0, %1}, %2;" : "=f"(lo), "=f"(hi) : "l"(p));
}
__device__ __forceinline__ unsigned long long fma2(unsigned long long a,
                                                   unsigned long long b,
                                                   unsigned long long c) {
    unsigned long long d;
    asm("fma.rn.f32x2 %0, %1, %2, %3;" : "=l"(d) : "l"(a), "l"(b), "l"(c));
    return d;
}
__device__ __forceinline__ unsigned long long add2(unsigned long long a,
                                                   unsigned long long b) {
    unsigned long long d;
    asm("add.rn.f32x2 %0, %1, %2;" : "=l"(d) : "l"(a), "l"(b));
    return d;
}
__device__ __forceinline__ unsigned long long mul2(unsigned long long a,
                                                   unsigned long long b) {
    unsigned long long d;
    asm("mul.rn.f32x2 %0, %1, %2;" : "=l"(d) : "l"(a), "l"(b));
    return d;
}

__global__ __launch_bounds__(RT) void sigmmd_row_kernel(
    const float* __restrict__ real_paths,
    const float* __restrict__ gen_paths)
{
    const int bid = blockIdx.x;
    const float* base = (bid < NROWS) ? real_paths : gen_paths;
    const int row = bid & (NROWS - 1);
    const float* p = base + (size_t)row * T_LEN;
    const int tid  = threadIdx.x;
    const int lane = tid & 31;
    const int w    = tid >> 5;

    __shared__ float s_w[RT / 32][3];

    // Warp w owns floats [w*1024, (w+1)*1024). Iteration i: lane-consecutive
    // float4 loads -> fully coalesced (4 L1 wavefronts per LDG.128).
    const float4* b4 = (const float4*)p + w * (WELEMS / 4);
    float4 v[8];
#pragma unroll
    for (int i = 0; i < 8; i++) v[i] = __ldcs(b4 + i * 32 + lane);

    // Predecessor of this warp's first element (only lane 0 uses it).
    // Warp 0 lane 0: phantom dx = 0 (prev = first element itself).
    float carry = 0.f;
    if (lane == 0) carry = (w == 0) ? v[0].x : __ldcs(p + w * WELEMS - 1);

    const unsigned long long NEG1 = pk2(-1.0f, -1.0f);
    unsigned long long qp = 0ull, cp = 0ull, spp = 0ull;   // (0.f,0.f) pairs
#pragma unroll
    for (int i = 0; i < 8; i++) {
        float4 c4 = v[i];
        float pl = __shfl_up_sync(0xffffffffu, c4.w, 1);   // prev lane's last
        float prev = (lane == 0) ? carry : pl;
        unsigned long long cur0 = pk2(c4.x, c4.y);
        unsigned long long cur1 = pk2(c4.z, c4.w);
        unsigned long long prv0 = pk2(prev, c4.x);
        unsigned long long prv1 = pk2(c4.y, c4.z);
        unsigned long long dx0 = fma2(prv0, NEG1, cur0);   // cur - prv
        unsigned long long dx1 = fma2(prv1, NEG1, cur1);
        unsigned long long t0 = mul2(dx0, dx0);
        unsigned long long t1 = mul2(dx1, dx1);
        qp  = add2(qp, add2(t0, t1));                      // sum dx^2
        cp  = fma2(t0, dx0, cp);                           // sum dx^3
        cp  = fma2(t1, dx1, cp);
        spp = add2(spp, add2(cur0, cur1));                 // sum p
        carry = __shfl_sync(0xffffffffu, c4.w, 31);        // for next iter lane 0
    }
    float ql, qh, cl, ch, sl, sh;
    upk2(qp, ql, qh); upk2(cp, cl, ch); upk2(spp, sl, sh);
    float q = ql + qh, c = cl + ch, sp = sl + sh;
    // sp must cover p[0..N-1] only: exclude the global last element
    if (tid == RT - 1) sp -= v[7].w;

    // Warp tree reduce (fp32, deterministic)
#pragma unroll
    for (int off = 16; off; off >>= 1) {
        q  += __shfl_down_sync(0xffffffffu, q,  off);
        c  += __shfl_down_sync(0xffffffffu, c,  off);
        sp += __shfl_down_sync(0xffffffffu, sp, off);
    }
    if (lane == 0) { s_w[w][0] = q; s_w[w][1] = c; s_w[w][2] = sp; }
    __syncthreads();

    if (tid == 0) {
        double Q = 0, C = 0, SP = 0;
#pragma unroll
        for (int k = 0; k < RT / 32; k++) {
            Q  += (double)s_w[k][0];
            C  += (double)s_w[k][1];
            SP += (double)s_w[k][2];
        }
        double p0 = (double)v[0].x;            // tid 0 owns p[0]
        double pN = (double)__ldg(p + T_LEN - 1);
        double S1 = pN - p0;
        g_feat[0][bid] = S1;                   // f1
        g_feat[1][bid] = pN - SP / 4095.0;     // f3
        g_feat[2][bid] = 0.5 * (S1 * S1 + Q);  // f4
        g_feat[3][bid] = Q;                    // f6
        g_feat[4][bid] = C;                    // f8
    }
}

// Fused reduce: 64 blocks x 128 threads, one row per thread (coalesced per
// feature plane). Each block tree-reduces to one partial; the last block to
// finish sums the 64 partials and writes the loss. Fixed summation order ->
// deterministic; counter self-resets -> graph-replay safe.
__global__ __launch_bounds__(ROWS_PB) void sigmmd_reduce_kernel(float* __restrict__ out)
{
    const int tid = threadIdx.x;
    const int r0 = blockIdx.x * ROWS_PB;
    const double sgn = (r0 < NROWS) ? 1.0 : -1.0;

    __shared__ double sm[ROWS_PB][NFEAT];
    __shared__ int s_last;
#pragma unroll
    for (int i = 0; i < NFEAT; i++) sm[tid][i] = g_feat[i][r0 + tid];
    __syncthreads();
    for (int stride = ROWS_PB / 2; stride; stride >>= 1) {
        if (tid < stride) {
#pragma unroll
            for (int i = 0; i < NFEAT; i++) sm[tid][i] += sm[tid + stride][i];
        }
        __syncthreads();
    }
    if (tid == 0) {
#pragma unroll
        for (int i = 0; i < NFEAT; i++) g_part[blockIdx.x][i] = sgn * sm[0][i];
        __threadfence();
        s_last = (atomicAdd(&g_ctr, 1) == P1_BLK - 1);
    }
    __syncthreads();

    if (s_last) {
        // Final reduction over 64 partials x 5 features.
        if (tid < P1_BLK) {
#pragma unroll
            for (int i = 0; i < NFEAT; i++) sm[tid][i] = g_part[tid][i];
        }
        __syncthreads();
        for (int stride = P1_BLK / 2; stride; stride >>= 1) {
            if (tid < stride) {
#pragma unroll
                for (int i = 0; i < NFEAT; i++) sm[tid][i] += sm[tid + stride][i];
            }
            __syncthreads();
        }
        if (tid == 0) {
            double loss = 0.0;
#pragma unroll
            for (int i = 0; i < NFEAT; i++) {
                double m = sm[0][i] / (double)NROWS;
                loss += m * m;
            }
            out[0] = (float)loss;
            g_ctr = 0;                 // reset for next graph replay
        }
    }
}

extern "C" void kernel_launch(void* const* d_in, const int* in_sizes, int n_in,
                              void* d_out, int out_size)
{
    const float* real_paths = (const float*)d_in[0];
    const float* gen_paths  = (const float*)d_in[1];
    float* out = (float*)d_out;

    sigmmd_row_kernel<<<NBLOCKS, RT>>>(real_paths, gen_paths);
    sigmmd_reduce_kernel<<<P1_BLK, ROWS_PB>>>(out);
}